// round 1
// baseline (speedup 1.0000x reference)
#include <cuda_runtime.h>

// WindowedSelfAttention3D — fully fused, one CTA per 4x4x4 window.
// x:[2,128,64,64,64] f32. T=64 tokens, C=128, 4 heads x 32.
// All GEMMs use packed fma.rn.f32x2 (2x fp32 rate on sm_103a vs 3-reg FFMA).

#define CCH   128
#define TOK   64
#define RS    132    // row stride (floats) for [64][128] smem buffers (pad 4)
#define SCS   68     // scores row stride
#define VOLS  262144 // 64*64*64

typedef unsigned long long u64t;

__device__ __forceinline__ u64t pk2(float lo, float hi) {
    u64t r; asm("mov.b64 %0, {%1, %2};" : "=l"(r) : "f"(lo), "f"(hi)); return r;
}
__device__ __forceinline__ void fma2(u64t& d, u64t a, u64t b) {
    asm("fma.rn.f32x2 %0, %1, %2, %0;" : "+l"(d) : "l"(a), "l"(b));
}
__device__ __forceinline__ float red2(u64t v) {
    float lo, hi; asm("mov.b64 {%0, %1}, %2;" : "=f"(lo), "=f"(hi) : "l"(v));
    return lo + hi;
}
__device__ __forceinline__ void unpk(u64t v, float& lo, float& hi) {
    asm("mov.b64 {%0, %1}, %2;" : "=f"(lo), "=f"(hi) : "l"(v));
}

// C = A[64xK=128] * B[64xK=128]^T tile, rm=rn=4 per thread, K packed in f32x2.
__device__ __forceinline__ void gemm_tile128(const float* __restrict__ A,
                                             const float* __restrict__ Bw,
                                             int tg, int ng, float out[4][4]) {
    u64t acc[4][4];
#pragma unroll
    for (int i = 0; i < 4; i++)
#pragma unroll
        for (int j = 0; j < 4; j++) acc[i][j] = 0ull;

#pragma unroll 4
    for (int k = 0; k < 128; k += 4) {
        u64t a0[4], a1[4], b0[4], b1[4];
#pragma unroll
        for (int i = 0; i < 4; i++) {
            ulonglong2 t = *(const ulonglong2*)(A + (tg * 4 + i) * RS + k);
            a0[i] = t.x; a1[i] = t.y;
        }
#pragma unroll
        for (int j = 0; j < 4; j++) {
            ulonglong2 t = *(const ulonglong2*)(Bw + (ng * 4 + j) * RS + k);
            b0[j] = t.x; b1[j] = t.y;
        }
#pragma unroll
        for (int i = 0; i < 4; i++)
#pragma unroll
            for (int j = 0; j < 4; j++) {
                fma2(acc[i][j], a0[i], b0[j]);
                fma2(acc[i][j], a1[i], b1[j]);
            }
    }
#pragma unroll
    for (int i = 0; i < 4; i++)
#pragma unroll
        for (int j = 0; j < 4; j++) out[i][j] = red2(acc[i][j]);
}

__global__ __launch_bounds__(256, 1)
void win_attn_kernel(const float* __restrict__ x,
                     const float* __restrict__ ln_g, const float* __restrict__ ln_b,
                     const float* __restrict__ Win,  const float* __restrict__ bin,
                     const float* __restrict__ Wout, const float* __restrict__ bout,
                     const float* __restrict__ Wc,   const float* __restrict__ bc,
                     float* __restrict__ out) {
    extern __shared__ float sm[];
    float* XW = sm;              // [64][132] original window (residual)
    float* XN = XW + TOK * RS;   // [64][132] LN output, later attn o
    float* Qb = XN + TOK * RS;   // [64][132] q, later y = xw + attn_out
    float* Kb = Qb + TOK * RS;   // [64][132]
    float* Vb = Kb + TOK * RS;   // [64][132]
    float* WT = Vb + TOK * RS;   // [64][132] weight tile
    float* SC = WT + TOK * RS;   // [64][68]  scores (per head)

    const int tid = threadIdx.x;
    const int wid = blockIdx.x;
    const int bb  = wid >> 12;
    const int rr  = wid & 4095;
    const int vd0 = (rr >> 8) * 4;
    const int vh0 = ((rr >> 4) & 15) * 4;
    const int vw0 = (rr & 15) * 4;
    const float* xb = x + (size_t)bb * ((size_t)CCH * VOLS);
    const size_t vox0 = (size_t)vd0 * 4096 + (size_t)vh0 * 64 + vw0;

    // ---- gather window into XW: float4 along contiguous dx runs ----
    for (int e = tid; e < TOK * CCH / 4; e += 256) {
        int c = e >> 4, tq = e & 15;
        int dz = tq >> 2, dy = tq & 3;
        float4 v = *(const float4*)(xb + (size_t)c * VOLS + vox0 + dz * 4096 + dy * 64);
        float* dst = XW + (dz * 16 + dy * 4) * RS + c;
        dst[0] = v.x; dst[RS] = v.y; dst[2 * RS] = v.z; dst[3 * RS] = v.w;
    }
    __syncthreads();

    // ---- LayerNorm over C=128 (4 threads per token) ----
    {
        int t = tid >> 2, sub = tid & 3;
        const float* row = XW + t * RS;
        float s = 0.f, ss = 0.f;
#pragma unroll 8
        for (int c = sub * 32; c < sub * 32 + 32; c++) { float v = row[c]; s += v; ss += v * v; }
        s  += __shfl_xor_sync(0xffffffffu, s, 1);  s  += __shfl_xor_sync(0xffffffffu, s, 2);
        ss += __shfl_xor_sync(0xffffffffu, ss, 1); ss += __shfl_xor_sync(0xffffffffu, ss, 2);
        float mu = s * (1.f / 128.f);
        float var = ss * (1.f / 128.f) - mu * mu;
        float rstd = rsqrtf(var + 1e-5f);
        float* nrow = XN + t * RS;
#pragma unroll 8
        for (int c = sub * 32; c < sub * 32 + 32; c++)
            nrow[c] = (row[c] - mu) * rstd * ln_g[c] + ln_b[c];
    }
    __syncthreads();

    const int tg = tid >> 4, ng = tid & 15;

    // ---- QKV projection: qkv[t][o] = sum_c xn[t][c] * Win[o][c] + bin[o] ----
    for (int nt = 0; nt < 6; nt++) {
        __syncthreads();
        for (int e = tid; e < 64 * 32; e += 256) {
            int o = e >> 5, k4 = e & 31;
            float4 w = *((const float4*)(Win + (size_t)(nt * 64 + o) * 128) + k4);
            *(float4*)(WT + o * RS + k4 * 4) = w;
        }
        __syncthreads();
        float accf[4][4];
        gemm_tile128(XN, WT, tg, ng, accf);
        float* dst = (nt < 2) ? Qb : (nt < 4) ? Kb : Vb;
        int cb = (nt & 1) * 64;
#pragma unroll
        for (int j = 0; j < 4; j++) {
            int cl = cb + ng * 4 + j;
            float bias = bin[nt * 64 + ng * 4 + j];
#pragma unroll
            for (int i = 0; i < 4; i++)
                dst[(tg * 4 + i) * RS + cl] = accf[i][j] + bias;
        }
    }

    // ---- attention per head (hd=32), o written into XN ----
    const float sc_norm = 0.17677669529663687f; // 1/sqrt(32)
    for (int hh = 0; hh < 4; hh++) {
        __syncthreads();
        // scores = q_h @ k_h^T * 1/sqrt(hd)   (64x64x32)
        {
            const float* Ah = Qb + hh * 32;
            const float* Bh = Kb + hh * 32;
            u64t acc[4][4];
#pragma unroll
            for (int i = 0; i < 4; i++)
#pragma unroll
                for (int j = 0; j < 4; j++) acc[i][j] = 0ull;
#pragma unroll
            for (int k = 0; k < 32; k += 4) {
                u64t a0[4], a1[4], b0[4], b1[4];
#pragma unroll
                for (int i = 0; i < 4; i++) {
                    ulonglong2 t = *(const ulonglong2*)(Ah + (tg * 4 + i) * RS + k);
                    a0[i] = t.x; a1[i] = t.y;
                }
#pragma unroll
                for (int j = 0; j < 4; j++) {
                    ulonglong2 t = *(const ulonglong2*)(Bh + (ng * 4 + j) * RS + k);
                    b0[j] = t.x; b1[j] = t.y;
                }
#pragma unroll
                for (int i = 0; i < 4; i++)
#pragma unroll
                    for (int j = 0; j < 4; j++) {
                        fma2(acc[i][j], a0[i], b0[j]);
                        fma2(acc[i][j], a1[i], b1[j]);
                    }
            }
#pragma unroll
            for (int i = 0; i < 4; i++)
#pragma unroll
                for (int j = 0; j < 4; j++)
                    SC[(tg * 4 + i) * SCS + ng * 4 + j] = red2(acc[i][j]) * sc_norm;
        }
        __syncthreads();
        // softmax over keys, 4 threads per row
        {
            int rrow = tid >> 2, sub = tid & 3;
            float* row = SC + rrow * SCS + sub * 16;
            float m = row[0];
#pragma unroll
            for (int c = 1; c < 16; c++) m = fmaxf(m, row[c]);
            m = fmaxf(m, __shfl_xor_sync(0xffffffffu, m, 1));
            m = fmaxf(m, __shfl_xor_sync(0xffffffffu, m, 2));
            float s = 0.f;
#pragma unroll
            for (int c = 0; c < 16; c++) { float e = __expf(row[c] - m); row[c] = e; s += e; }
            s += __shfl_xor_sync(0xffffffffu, s, 1);
            s += __shfl_xor_sync(0xffffffffu, s, 2);
            float inv = 1.f / s;
#pragma unroll
            for (int c = 0; c < 16; c++) row[c] *= inv;
        }
        __syncthreads();
        // o_h = attn @ v_h  (64x32x64), outer-product over keys
        {
            int tg2 = tid >> 3, ng2 = tid & 7;
            u64t acc[2][2] = {{0ull, 0ull}, {0ull, 0ull}};
#pragma unroll 8
            for (int k = 0; k < 64; k++) {
                float a0 = SC[(tg2 * 2 + 0) * SCS + k];
                float a1 = SC[(tg2 * 2 + 1) * SCS + k];
                ulonglong2 bv = *(const ulonglong2*)(Vb + k * RS + hh * 32 + ng2 * 4);
                u64t ap0 = pk2(a0, a0), ap1 = pk2(a1, a1);
                fma2(acc[0][0], ap0, bv.x); fma2(acc[0][1], ap0, bv.y);
                fma2(acc[1][0], ap1, bv.x); fma2(acc[1][1], ap1, bv.y);
            }
#pragma unroll
            for (int i = 0; i < 2; i++) {
                float* dst = XN + (tg2 * 2 + i) * RS + hh * 32 + ng2 * 4;
                float lo, hi;
                unpk(acc[i][0], lo, hi); dst[0] = lo; dst[1] = hi;
                unpk(acc[i][1], lo, hi); dst[2] = lo; dst[3] = hi;
            }
        }
    }

    // ---- out_proj: y = xw + o @ Wout^T + bout   (into Qb) ----
    for (int nt = 0; nt < 2; nt++) {
        __syncthreads();
        for (int e = tid; e < 64 * 32; e += 256) {
            int o = e >> 5, k4 = e & 31;
            float4 w = *((const float4*)(Wout + (size_t)(nt * 64 + o) * 128) + k4);
            *(float4*)(WT + o * RS + k4 * 4) = w;
        }
        __syncthreads();
        float accf[4][4];
        gemm_tile128(XN, WT, tg, ng, accf);
#pragma unroll
        for (int j = 0; j < 4; j++) {
            int cc = nt * 64 + ng * 4 + j;
            float bias = bout[cc];
#pragma unroll
            for (int i = 0; i < 4; i++) {
                int t = tg * 4 + i;
                Qb[t * RS + cc] = XW[t * RS + cc] + accf[i][j] + bias;
            }
        }
    }

    // ---- 1x1x1 conv + residual, scatter to global ----
    float* outp = out + (size_t)bb * ((size_t)CCH * VOLS);
    for (int nt = 0; nt < 2; nt++) {
        __syncthreads();
        for (int e = tid; e < 64 * 32; e += 256) {
            int o = e >> 5, k4 = e & 31;
            float4 w = *((const float4*)(Wc + (size_t)(nt * 64 + o) * 128) + k4);
            *(float4*)(WT + o * RS + k4 * 4) = w;
        }
        __syncthreads();
        float accf[4][4];
        gemm_tile128(Qb, WT, tg, ng, accf);
        int t0 = tg * 4;
        int dz = t0 >> 4, dy = (t0 >> 2) & 3;
#pragma unroll
        for (int j = 0; j < 4; j++) {
            int cc = nt * 64 + ng * 4 + j;
            float bias = bc[cc];
            float4 o4;
            o4.x = accf[0][j] + bias + XW[(t0 + 0) * RS + cc];
            o4.y = accf[1][j] + bias + XW[(t0 + 1) * RS + cc];
            o4.z = accf[2][j] + bias + XW[(t0 + 2) * RS + cc];
            o4.w = accf[3][j] + bias + XW[(t0 + 3) * RS + cc];
            *(float4*)(outp + (size_t)cc * VOLS + vox0 + dz * 4096 + dy * 64) = o4;
        }
    }
}

static const int SMEM_BYTES = (6 * TOK * RS + TOK * SCS) * 4; // 220160 B

extern "C" void kernel_launch(void* const* d_in, const int* in_sizes, int n_in,
                              void* d_out, int out_size) {
    const float* x    = (const float*)d_in[0];
    const float* ln_g = (const float*)d_in[1];
    const float* ln_b = (const float*)d_in[2];
    const float* Win  = (const float*)d_in[3];
    const float* bin  = (const float*)d_in[4];
    const float* Wout = (const float*)d_in[5];
    const float* bout = (const float*)d_in[6];
    const float* Wc   = (const float*)d_in[7];
    const float* bc   = (const float*)d_in[8];
    float* out = (float*)d_out;

    cudaFuncSetAttribute(win_attn_kernel,
                         cudaFuncAttributeMaxDynamicSharedMemorySize, SMEM_BYTES);
    win_attn_kernel<<<8192, 256, SMEM_BYTES>>>(x, ln_g, ln_b, Win, bin,
                                               Wout, bout, Wc, bc, out);
}